// round 5
// baseline (speedup 1.0000x reference)
#include <cuda_runtime.h>
#include <cuda_fp16.h>

// Problem constants
#define FT_B 4
#define FT_C 256
#define FT_T 16
#define FT_H 64
#define FT_W 64
#define SPATIAL (FT_T*FT_H*FT_W)          // 65536 per (b,c)
#define FT_PER_B ((size_t)SPATIAL*FT_C)   // 16,777,216 elements per batch in fT

#define CG 64                              // channels per block (32 lanes x 2ch)

// Channels-last fp16 scratch: fT[b][t][h][w][c]  (134 MB static device array)
__device__ __half g_fT[(size_t)FT_B * FT_T * FT_H * FT_W * FT_C];

// ---------------------------------------------------------------------------
// Kernel 1: transpose (B,C,THW) f32 -> (B,THW,C) f16, tiled 32x32.
// ---------------------------------------------------------------------------
__global__ void transpose_kernel(const float* __restrict__ f) {
    __shared__ float tile[32][33];
    const int b  = blockIdx.z;
    const int s0 = blockIdx.x * 32;   // spatial base (t*4096 + h*64 + w)
    const int c0 = blockIdx.y * 32;   // channel base
    const int tx = threadIdx.x, ty = threadIdx.y;

    const float* src = f + (size_t)b * FT_C * SPATIAL;
    #pragma unroll
    for (int j = 0; j < 32; j += 8)
        tile[ty + j][tx] = src[(size_t)(c0 + ty + j) * SPATIAL + s0 + tx];
    __syncthreads();
    __half* dst = g_fT + (size_t)b * SPATIAL * FT_C;
    #pragma unroll
    for (int j = 0; j < 32; j += 8)
        dst[(size_t)(s0 + ty + j) * FT_C + c0 + tx] = __float2half(tile[tx][ty + j]);
}

// ---------------------------------------------------------------------------
// Kernel 2: fused RoIAlign3D + avg_pool3d(k=2,s=1).
// Block = 8 warps x 32 lanes. warp = y-sample row, lane = channel PAIR
// (half2 gathers, fp32 math). grid = (n_rois, 4): roi varies FASTEST so
// concurrently resident blocks work in the SAME 64-channel slice
// (~33 MB across 4 batches -> L2 resident -> compulsory-only DRAM).
// Own x-pooled row stays in registers; only the neighbor row crosses smem
// (double-buffered). Staging tile is bank-conflict-free [pix][lane].
// ---------------------------------------------------------------------------
struct __align__(16) AxisEntry { int o0; int o1; float w0; float w1; };

__global__ __launch_bounds__(256, 4)
void roialign_pool_kernel(const float* __restrict__ rois,
                          float* __restrict__ out) {
    __shared__ AxisEntry sT[5], sY[8], sX[8];
    __shared__ float2 srows[2][8][7][32];   // [buf][ysample][xout][lane] 28672 B
    __shared__ float2 staging2[49][33];     // [pix][lanepair], padded   12936 B

    const int r   = blockIdx.x;             // roi (fastest-varying)
    const int g   = blockIdx.y;             // channel group 0..3
    const int tid = threadIdx.x;
    const int w   = tid >> 5;               // warp id = y-sample row
    const int l   = tid & 31;               // lane    = channel pair
    const float* roi = rois + r * 7;

    // --- axis sample tables (matches reference _axis_samples) ---
    if (tid < 21) {
        float start, end, fsize; int n, k, stride; AxisEntry* dstE;
        if (tid < 5)       { k = tid;      start = roi[5];          end = roi[6];          fsize = (float)FT_T; n = 5; stride = FT_H*FT_W*FT_C; dstE = &sT[k]; }
        else if (tid < 13) { k = tid - 5;  start = roi[2]*0.0625f;  end = roi[4]*0.0625f;  fsize = (float)FT_H; n = 8; stride = FT_W*FT_C;      dstE = &sY[k]; }
        else               { k = tid - 13; start = roi[1]*0.0625f;  end = roi[3]*0.0625f;  fsize = (float)FT_W; n = 8; stride = FT_C;           dstE = &sX[k]; }
        float length = fmaxf(end - start + 1.0f, 1.0f);
        float step   = length / (float)(n - 1);
        float coord  = start + step * (float)k;
        float valid  = (coord >= 0.0f && coord < fsize) ? 1.0f : 0.0f;
        float lo     = floorf(coord);
        lo = fminf(fmaxf(lo, 0.0f), fsize - 1.0f);
        float frac   = coord - lo;
        int loi = (int)lo;
        int hii = min(loi + 1, (int)fsize - 1);
        dstE->o0 = loi * stride;
        dstE->o1 = hii * stride;
        dstE->w0 = (1.0f - frac) * valid;
        dstE->w1 = frac * valid;
    }
    __syncthreads();

    const int b  = (int)roi[0];
    const int c0 = g * CG;
    const __half* bp = g_fT + (size_t)b * FT_PER_B + c0 + 2 * l;

    // this warp's y entry (fixed for all t)
    const int4  y4  = *reinterpret_cast<const int4*>(&sY[w]);
    const int   yO0 = y4.x, yO1 = y4.y;
    const float yW0 = __int_as_float(y4.z), yW1 = __int_as_float(y4.w);

    float2 prevT[7];   // pooled (x,y) row for previous t-sample (warps 0..6)

    for (int ts = 0; ts < 5; ++ts) {
        const int buf = ts & 1;
        const int4  t4  = *reinterpret_cast<const int4*>(&sT[ts]);
        const int   tO0 = t4.x, tO1 = t4.y;
        const float tW0 = __int_as_float(t4.z), tW1 = __int_as_float(t4.w);

        const __half* p00 = bp + tO0 + yO0;
        const __half* p01 = bp + tO0 + yO1;
        const __half* p10 = bp + tO1 + yO0;
        const __half* p11 = bp + tO1 + yO1;
        const float w00 = tW0 * yW0, w01 = tW0 * yW1;
        const float w10 = tW1 * yW0, w11 = tW1 * yW1;

        // gather + x-interp + x-pool (8 samples -> 7 pooled, streaming)
        float2 rp[7];
        float2 vprev;
        #pragma unroll
        for (int xs = 0; xs < 8; ++xs) {
            const int4  x4  = *reinterpret_cast<const int4*>(&sX[xs]);
            const int   xO0 = x4.x, xO1 = x4.y;
            const float xW0 = __int_as_float(x4.z), xW1 = __int_as_float(x4.w);

            float2 a0 = __half22float2(__ldg(reinterpret_cast<const __half2*>(p00 + xO0)));
            float2 a1 = __half22float2(__ldg(reinterpret_cast<const __half2*>(p00 + xO1)));
            float2 b0 = __half22float2(__ldg(reinterpret_cast<const __half2*>(p01 + xO0)));
            float2 b1 = __half22float2(__ldg(reinterpret_cast<const __half2*>(p01 + xO1)));
            float2 c0v = __half22float2(__ldg(reinterpret_cast<const __half2*>(p10 + xO0)));
            float2 c1v = __half22float2(__ldg(reinterpret_cast<const __half2*>(p10 + xO1)));
            float2 d0 = __half22float2(__ldg(reinterpret_cast<const __half2*>(p11 + xO0)));
            float2 d1 = __half22float2(__ldg(reinterpret_cast<const __half2*>(p11 + xO1)));

            float2 v;
            v.x = w00 * (xW0 * a0.x + xW1 * a1.x)
                + w01 * (xW0 * b0.x + xW1 * b1.x)
                + w10 * (xW0 * c0v.x + xW1 * c1v.x)
                + w11 * (xW0 * d0.x + xW1 * d1.x);
            v.y = w00 * (xW0 * a0.y + xW1 * a1.y)
                + w01 * (xW0 * b0.y + xW1 * b1.y)
                + w10 * (xW0 * c0v.y + xW1 * c1v.y)
                + w11 * (xW0 * d0.y + xW1 * d1.y);

            if (xs > 0) {
                rp[xs - 1].x = vprev.x + v.x;
                rp[xs - 1].y = vprev.y + v.y;
            }
            vprev = v;
        }

        // publish this warp's pooled row (double-buffered)
        #pragma unroll
        for (int xo = 0; xo < 7; ++xo)
            srows[buf][w][xo][l] = rp[xo];
        __syncthreads();   // srows[buf] visible

        // y-pool using own regs + neighbor's smem row; t-pool when ts>0
        if (w < 7) {
            #pragma unroll
            for (int xo = 0; xo < 7; ++xo) {
                float2 nb = srows[buf][w + 1][xo][l];
                float2 cur;
                cur.x = rp[xo].x + nb.x;
                cur.y = rp[xo].y + nb.y;
                if (ts > 0) {
                    float2 o;
                    o.x = (prevT[xo].x + cur.x) * 0.125f;
                    o.y = (prevT[xo].y + cur.y) * 0.125f;
                    staging2[w * 7 + xo][l] = o;   // conflict-free STS.64
                }
                prevT[xo] = cur;
            }
        }

        if (ts > 0) {
            __syncthreads();   // staging visible
            // coalesced stream-out: out[r][c0+cc][to][pix], to = ts-1
            const size_t obase = ((size_t)r * FT_C + c0) * 196 + (size_t)(ts - 1) * 49;
            const float* stg = reinterpret_cast<const float*>(staging2);
            #pragma unroll
            for (int k = 0; k < 13; ++k) {
                int idx = tid + k * 256;
                if (idx < CG * 49) {
                    int cc  = idx / 49;
                    int pix = idx - cc * 49;
                    out[obase + (size_t)cc * 196 + pix] = stg[pix * 66 + cc];
                }
            }
        }
    }
}

// ---------------------------------------------------------------------------
extern "C" void kernel_launch(void* const* d_in, const int* in_sizes, int n_in,
                              void* d_out, int out_size) {
    const float* features = (const float*)d_in[0];
    const float* rois     = (const float*)d_in[1];
    float* out            = (float*)d_out;
    const int n_rois = in_sizes[1] / 7;

    dim3 tb(32, 8);
    dim3 tg(SPATIAL / 32, FT_C / 32, FT_B);
    transpose_kernel<<<tg, tb>>>(features);

    roialign_pool_kernel<<<dim3(n_rois, FT_C / CG), 256>>>(rois, out);
}

// round 6
// speedup vs baseline: 1.1476x; 1.1476x over previous
#include <cuda_runtime.h>
#include <cuda_fp16.h>

// Problem constants
#define FT_B 4
#define FT_C 256
#define FT_T 16
#define FT_H 64
#define FT_W 64
#define SPATIAL (FT_T*FT_H*FT_W)          // 65536 per (b,c)
#define FT_PER_B ((size_t)SPATIAL*FT_C)   // 16,777,216 elements per batch in fT

#define CG 64                              // channels per block (32 lanes x 2ch)

// Channels-last fp16 scratch: fT[b][t][h][w][c]  (134 MB static device array)
__device__ __half g_fT[(size_t)FT_B * FT_T * FT_H * FT_W * FT_C];

// ---------------------------------------------------------------------------
// Kernel 1: transpose (B,C,THW) f32 -> (B,THW,C) f16, tiled 32x32.
// ---------------------------------------------------------------------------
__global__ void transpose_kernel(const float* __restrict__ f) {
    __shared__ float tile[32][33];
    const int b  = blockIdx.z;
    const int s0 = blockIdx.x * 32;   // spatial base (t*4096 + h*64 + w)
    const int c0 = blockIdx.y * 32;   // channel base
    const int tx = threadIdx.x, ty = threadIdx.y;

    const float* src = f + (size_t)b * FT_C * SPATIAL;
    #pragma unroll
    for (int j = 0; j < 32; j += 8)
        tile[ty + j][tx] = src[(size_t)(c0 + ty + j) * SPATIAL + s0 + tx];
    __syncthreads();
    __half* dst = g_fT + (size_t)b * SPATIAL * FT_C;
    #pragma unroll
    for (int j = 0; j < 32; j += 8)
        dst[(size_t)(s0 + ty + j) * FT_C + c0 + tx] = __float2half(tile[tx][ty + j]);
}

// ---------------------------------------------------------------------------
// Kernel 2: fused RoIAlign3D + avg_pool3d(k=2,s=1).
// Block = 8 warps x 32 lanes. warp = y-sample row, lane = channel PAIR
// (half2 gathers, fp32 math). grid = (n_rois, 4): roi varies FASTEST so
// concurrently resident blocks work in the SAME 64-channel slice
// (~33 MB across 4 batches -> L2 resident).
// Register-state minimized for occupancy (5 CTAs/SM): NO cross-ts register
// plane. The unscaled pooled plane for t-sample ts goes to staging[ts&1];
// stream-out of output plane (ts-1) reads BOTH buffers and scales by 1/8.
// srows is single-buffered (barriers already separate readers/writers).
// ---------------------------------------------------------------------------
struct __align__(16) AxisEntry { int o0; int o1; float w0; float w1; };

__global__ __launch_bounds__(256, 5)
void roialign_pool_kernel(const float* __restrict__ rois,
                          float* __restrict__ out) {
    __shared__ AxisEntry sT[5], sY[8], sX[8];
    __shared__ float2 srows[8][7][32];      // [ysample][xout][lane]   14336 B
    __shared__ float2 staging2[2][49][33];  // [buf][pix][lanepair]    25872 B

    const int r   = blockIdx.x;             // roi (fastest-varying)
    const int g   = blockIdx.y;             // channel group 0..3
    const int tid = threadIdx.x;
    const int w   = tid >> 5;               // warp id = y-sample row
    const int l   = tid & 31;               // lane    = channel pair
    const float* roi = rois + r * 7;

    // --- axis sample tables (matches reference _axis_samples) ---
    if (tid < 21) {
        float start, end, fsize; int n, k, stride; AxisEntry* dstE;
        if (tid < 5)       { k = tid;      start = roi[5];          end = roi[6];          fsize = (float)FT_T; n = 5; stride = FT_H*FT_W*FT_C; dstE = &sT[k]; }
        else if (tid < 13) { k = tid - 5;  start = roi[2]*0.0625f;  end = roi[4]*0.0625f;  fsize = (float)FT_H; n = 8; stride = FT_W*FT_C;      dstE = &sY[k]; }
        else               { k = tid - 13; start = roi[1]*0.0625f;  end = roi[3]*0.0625f;  fsize = (float)FT_W; n = 8; stride = FT_C;           dstE = &sX[k]; }
        float length = fmaxf(end - start + 1.0f, 1.0f);
        float step   = length / (float)(n - 1);
        float coord  = start + step * (float)k;
        float valid  = (coord >= 0.0f && coord < fsize) ? 1.0f : 0.0f;
        float lo     = floorf(coord);
        lo = fminf(fmaxf(lo, 0.0f), fsize - 1.0f);
        float frac   = coord - lo;
        int loi = (int)lo;
        int hii = min(loi + 1, (int)fsize - 1);
        dstE->o0 = loi * stride;
        dstE->o1 = hii * stride;
        dstE->w0 = (1.0f - frac) * valid;
        dstE->w1 = frac * valid;
    }
    __syncthreads();

    const int b  = (int)roi[0];
    const int c0 = g * CG;
    const __half* bp = g_fT + (size_t)b * FT_PER_B + c0 + 2 * l;

    // this warp's y entry (fixed for all t)
    const int4  y4  = *reinterpret_cast<const int4*>(&sY[w]);
    const int   yO0 = y4.x, yO1 = y4.y;
    const float yW0 = __int_as_float(y4.z), yW1 = __int_as_float(y4.w);

    for (int ts = 0; ts < 5; ++ts) {
        const int buf = ts & 1;
        const int4  t4  = *reinterpret_cast<const int4*>(&sT[ts]);
        const int   tO0 = t4.x, tO1 = t4.y;
        const float tW0 = __int_as_float(t4.z), tW1 = __int_as_float(t4.w);

        const __half* p00 = bp + tO0 + yO0;
        const __half* p01 = bp + tO0 + yO1;
        const __half* p10 = bp + tO1 + yO0;
        const __half* p11 = bp + tO1 + yO1;
        const float w00 = tW0 * yW0, w01 = tW0 * yW1;
        const float w10 = tW1 * yW0, w11 = tW1 * yW1;

        // gather + x-interp + x-pool (8 samples -> 7 pooled, streaming)
        float2 rp[7];
        float2 vprev;
        #pragma unroll
        for (int xs = 0; xs < 8; ++xs) {
            const int4  x4  = *reinterpret_cast<const int4*>(&sX[xs]);
            const int   xO0 = x4.x, xO1 = x4.y;
            const float xW0 = __int_as_float(x4.z), xW1 = __int_as_float(x4.w);

            float2 a0 = __half22float2(__ldg(reinterpret_cast<const __half2*>(p00 + xO0)));
            float2 a1 = __half22float2(__ldg(reinterpret_cast<const __half2*>(p00 + xO1)));
            float2 b0 = __half22float2(__ldg(reinterpret_cast<const __half2*>(p01 + xO0)));
            float2 b1 = __half22float2(__ldg(reinterpret_cast<const __half2*>(p01 + xO1)));
            float2 c0v = __half22float2(__ldg(reinterpret_cast<const __half2*>(p10 + xO0)));
            float2 c1v = __half22float2(__ldg(reinterpret_cast<const __half2*>(p10 + xO1)));
            float2 d0 = __half22float2(__ldg(reinterpret_cast<const __half2*>(p11 + xO0)));
            float2 d1 = __half22float2(__ldg(reinterpret_cast<const __half2*>(p11 + xO1)));

            float2 v;
            v.x = w00 * (xW0 * a0.x + xW1 * a1.x)
                + w01 * (xW0 * b0.x + xW1 * b1.x)
                + w10 * (xW0 * c0v.x + xW1 * c1v.x)
                + w11 * (xW0 * d0.x + xW1 * d1.x);
            v.y = w00 * (xW0 * a0.y + xW1 * a1.y)
                + w01 * (xW0 * b0.y + xW1 * b1.y)
                + w10 * (xW0 * c0v.y + xW1 * c1v.y)
                + w11 * (xW0 * d0.y + xW1 * d1.y);

            if (xs > 0) {
                rp[xs - 1].x = vprev.x + v.x;
                rp[xs - 1].y = vprev.y + v.y;
            }
            vprev = v;
        }

        // publish this warp's pooled row
        #pragma unroll
        for (int xo = 0; xo < 7; ++xo)
            srows[w][xo][l] = rp[xo];
        __syncthreads();   // srows visible (also: staging[buf] readers done)

        // y-pool using own regs + neighbor's smem row -> unscaled plane
        if (w < 7) {
            #pragma unroll
            for (int xo = 0; xo < 7; ++xo) {
                float2 nb = srows[w + 1][xo][l];
                float2 cur;
                cur.x = rp[xo].x + nb.x;
                cur.y = rp[xo].y + nb.y;
                staging2[buf][w * 7 + xo][l] = cur;   // conflict-free STS.64
            }
        }
        __syncthreads();   // staging[buf] visible; srows readers done

        if (ts > 0) {
            // stream-out plane (ts-1) = (staging[0]+staging[1]) * 0.125
            const size_t obase = ((size_t)r * FT_C + c0) * 196 + (size_t)(ts - 1) * 49;
            const float* sA = reinterpret_cast<const float*>(staging2[0]);
            const float* sB = reinterpret_cast<const float*>(staging2[1]);
            #pragma unroll
            for (int k = 0; k < 13; ++k) {
                int idx = tid + k * 256;
                if (idx < CG * 49) {
                    int cc  = idx / 49;
                    int pix = idx - cc * 49;
                    float v = (sA[pix * 66 + cc] + sB[pix * 66 + cc]) * 0.125f;
                    __stcs(&out[obase + (size_t)cc * 196 + pix], v);
                }
            }
        }
    }
}

// ---------------------------------------------------------------------------
extern "C" void kernel_launch(void* const* d_in, const int* in_sizes, int n_in,
                              void* d_out, int out_size) {
    const float* features = (const float*)d_in[0];
    const float* rois     = (const float*)d_in[1];
    float* out            = (float*)d_out;
    const int n_rois = in_sizes[1] / 7;

    dim3 tb(32, 8);
    dim3 tg(SPATIAL / 32, FT_C / 32, FT_B);
    transpose_kernel<<<tg, tb>>>(features);

    roialign_pool_kernel<<<dim3(n_rois, FT_C / CG), 256>>>(rois, out);
}